// round 1
// baseline (speedup 1.0000x reference)
#include <cuda_runtime.h>
#include <cuda_bf16.h>
#include <math.h>

#define BB 4
#define SS 256
#define VV 64
#define LP1 11
#define HH 128
#define NHH 8
#define DHH 16
#define NLL 3
#define BT 1024   // B*S

// ---------------- scratch (static device globals; no runtime allocation) ----
__device__ float g_adj[VV * VV * LP1];
__device__ float g_z0[(long)VV * BT * HH];
__device__ float g_z1[(long)VV * BT * HH];
__device__ float g_qb[(long)VV * BT * HH];
__device__ float g_kb[(long)VV * BT * HH];
__device__ float g_vb[(long)VV * BT * HH];
__device__ float g_ob[(long)VV * BT * HH];

// ---------------- kernel 0: sigmoid of adjacency logits ---------------------
__global__ void sigmoid_kernel(const float* __restrict__ logits, float* __restrict__ adj, int n) {
    int i = blockIdx.x * blockDim.x + threadIdx.x;
    if (i < n) {
        float x = logits[i];
        adj[i] = 1.f / (1.f + __expf(-x));
    }
}

// ---------------- kernel 1: causal input z[b,t,i,h] -------------------------
// z[(i*BT+bt)*H + h] = sum_s A[i,s]*var_emb[s,h] + sum_l Bl[i,l]*temp_emb[l,h]
// A[i,s] = sum_l xlag[s,l]*adj[s,i,l] ; Bl[i,l] = sum_s xlag[s,l]*adj[s,i,l]
__global__ void __launch_bounds__(128) causal_input_kernel(
    const float* __restrict__ x,
    const float* __restrict__ var_emb,
    const float* __restrict__ temp_emb,
    const float* __restrict__ adj,
    float* __restrict__ z)
{
    __shared__ float xlag[VV][12];
    __shared__ float Asm[VV][65];
    __shared__ float Blsm[VV][12];

    int bt = blockIdx.x;
    int b = bt >> 8;
    int t = bt & 255;
    int tid = threadIdx.x;

    for (int i = tid; i < VV * LP1; i += 128) {
        int s = i / LP1, l = i % LP1;
        xlag[s][l] = (t >= l) ? x[(b * SS + (t - l)) * VV + s] : 0.f;
    }
    __syncthreads();

    for (int i = tid; i < VV * VV; i += 128) {
        int s = i >> 6, ii = i & 63;
        const float* ap = adj + (s * VV + ii) * LP1;
        float a = 0.f;
#pragma unroll
        for (int l = 0; l < LP1; l++) a += xlag[s][l] * ap[l];
        Asm[ii][s] = a;
    }
    for (int i = tid; i < VV * LP1; i += 128) {
        int ii = i / LP1, l = i % LP1;
        float a = 0.f;
#pragma unroll 8
        for (int s = 0; s < VV; s++) a += xlag[s][l] * adj[(s * VV + ii) * LP1 + l];
        Blsm[ii][l] = a;
    }
    __syncthreads();

    int h = tid;  // 128 threads == H
    for (int ii = 0; ii < VV; ii++) {
        float acc = 0.f;
#pragma unroll 8
        for (int s = 0; s < VV; s++) acc += Asm[ii][s] * var_emb[s * HH + h];
#pragma unroll
        for (int l = 0; l < LP1; l++) acc += Blsm[ii][l] * temp_emb[l * HH + h];
        z[((long)ii * BT + bt) * HH + h] = acc;
    }
}

// ---------------- kernel 2: per-variable GEMM (+opt LN+GELU epilogue) -------
// in, out layout: [v][bt][h] (contiguous per variable). W: base + v*wStride, [h_in][h_out].
template <bool LN_GELU>
__global__ void __launch_bounds__(256) pv_gemm(
    const float* __restrict__ in,
    const float* __restrict__ Wb, long wStride,
    const float* __restrict__ biasB, int bStride,
    const float* __restrict__ gB, const float* __restrict__ betaB,
    float* __restrict__ out)
{
    __shared__ float Zt[64][33];
    __shared__ float Wt[32][128];

    int v = blockIdx.y;
    int row0 = blockIdx.x * 64;
    const float* W = Wb + (long)v * wStride;
    const float* inV = in + ((long)v * BT + row0) * HH;
    float* outV = out + ((long)v * BT + row0) * HH;
    const float* bias = biasB + (long)v * bStride;

    int tid = threadIdx.x;
    int rg = tid >> 4;      // 0..15 (4 rows each)
    int cg = tid & 15;      // 0..15 (8 cols each)

    float acc[4][8];
#pragma unroll
    for (int r = 0; r < 4; r++)
#pragma unroll
        for (int c = 0; c < 8; c++) acc[r][c] = 0.f;

    for (int kt = 0; kt < 4; kt++) {
        for (int i = tid; i < 64 * 32; i += 256) {
            int r = i >> 5, c = i & 31;
            Zt[r][c] = inV[r * HH + kt * 32 + c];
        }
        for (int i = tid; i < 32 * 128; i += 256) {
            int kk = i >> 7, c = i & 127;
            Wt[kk][c] = W[(kt * 32 + kk) * HH + c];
        }
        __syncthreads();
#pragma unroll
        for (int kk = 0; kk < 32; kk++) {
            float zr[4];
#pragma unroll
            for (int r = 0; r < 4; r++) zr[r] = Zt[rg * 4 + r][kk];
            float4 w0 = *(const float4*)&Wt[kk][cg * 8];
            float4 w1 = *(const float4*)&Wt[kk][cg * 8 + 4];
            float wv[8] = {w0.x, w0.y, w0.z, w0.w, w1.x, w1.y, w1.z, w1.w};
#pragma unroll
            for (int r = 0; r < 4; r++)
#pragma unroll
                for (int c = 0; c < 8; c++) acc[r][c] += zr[r] * wv[c];
        }
        __syncthreads();
    }

    int colBase = cg * 8;
    float bvals[8];
#pragma unroll
    for (int c = 0; c < 8; c++) bvals[c] = bias[colBase + c];
#pragma unroll
    for (int r = 0; r < 4; r++)
#pragma unroll
        for (int c = 0; c < 8; c++) acc[r][c] += bvals[c];

    if (LN_GELU) {
        const float* gp = gB + (long)v * bStride;
        const float* bp = betaB + (long)v * bStride;
        float gv[8], bev[8];
#pragma unroll
        for (int c = 0; c < 8; c++) { gv[c] = gp[colBase + c]; bev[c] = bp[colBase + c]; }
#pragma unroll
        for (int r = 0; r < 4; r++) {
            float sum = 0.f, sq = 0.f;
#pragma unroll
            for (int c = 0; c < 8; c++) { sum += acc[r][c]; sq += acc[r][c] * acc[r][c]; }
#pragma unroll
            for (int m = 1; m < 16; m <<= 1) {
                sum += __shfl_xor_sync(0xffffffffu, sum, m);
                sq  += __shfl_xor_sync(0xffffffffu, sq, m);
            }
            float mu = sum * (1.f / 128.f);
            float var = sq * (1.f / 128.f) - mu * mu;
            float inv = rsqrtf(var + 1e-5f);
#pragma unroll
            for (int c = 0; c < 8; c++) {
                float xn = (acc[r][c] - mu) * inv * gv[c] + bev[c];
                acc[r][c] = 0.5f * xn * (1.f + erff(xn * 0.70710678118654752f));
            }
        }
    }

#pragma unroll
    for (int r = 0; r < 4; r++) {
        float4 s0 = make_float4(acc[r][0], acc[r][1], acc[r][2], acc[r][3]);
        float4 s1 = make_float4(acc[r][4], acc[r][5], acc[r][6], acc[r][7]);
        *(float4*)&outV[(rg * 4 + r) * HH + colBase]     = s0;
        *(float4*)&outV[(rg * 4 + r) * HH + colBase + 4] = s1;
    }
}

// ---------------- kernel 3: attention per (b,v,head), online softmax --------
__global__ void __launch_bounds__(256) attn_kernel(
    const float* __restrict__ q, const float* __restrict__ k,
    const float* __restrict__ vv, float* __restrict__ o)
{
    __shared__ float4 K4[SS * 4];
    __shared__ float4 V4[SS * 4];

    int g = blockIdx.x;
    int b = g / (VV * NHH);
    int rem = g % (VV * NHH);
    int v = rem / NHH;
    int nh = rem % NHH;

    long base = ((long)v * BT + (long)b * SS) * HH + nh * DHH;
    int t = threadIdx.x;

#pragma unroll
    for (int d4 = 0; d4 < 4; d4++) {
        K4[t * 4 + d4] = *(const float4*)(k  + base + (long)t * HH + d4 * 4);
        V4[t * 4 + d4] = *(const float4*)(vv + base + (long)t * HH + d4 * 4);
    }
    float4 q0 = *(const float4*)(q + base + (long)t * HH + 0);
    float4 q1 = *(const float4*)(q + base + (long)t * HH + 4);
    float4 q2 = *(const float4*)(q + base + (long)t * HH + 8);
    float4 q3 = *(const float4*)(q + base + (long)t * HH + 12);
    __syncthreads();

    float m = -1e30f, l = 0.f;
    float4 o0 = {0,0,0,0}, o1 = {0,0,0,0}, o2 = {0,0,0,0}, o3 = {0,0,0,0};

    for (int j = 0; j < SS; j++) {
        float4 k0 = K4[j * 4 + 0], k1 = K4[j * 4 + 1], k2 = K4[j * 4 + 2], k3 = K4[j * 4 + 3];
        float s = q0.x*k0.x + q0.y*k0.y + q0.z*k0.z + q0.w*k0.w
                + q1.x*k1.x + q1.y*k1.y + q1.z*k1.z + q1.w*k1.w
                + q2.x*k2.x + q2.y*k2.y + q2.z*k2.z + q2.w*k2.w
                + q3.x*k3.x + q3.y*k3.y + q3.z*k3.z + q3.w*k3.w;
        s *= 0.25f;  // 1/sqrt(16)
        float mn = fmaxf(m, s);
        float corr = __expf(m - mn);
        float p = __expf(s - mn);
        l = l * corr + p;
        float4 v0 = V4[j * 4 + 0], v1 = V4[j * 4 + 1], v2 = V4[j * 4 + 2], v3 = V4[j * 4 + 3];
        o0.x = o0.x * corr + p * v0.x; o0.y = o0.y * corr + p * v0.y;
        o0.z = o0.z * corr + p * v0.z; o0.w = o0.w * corr + p * v0.w;
        o1.x = o1.x * corr + p * v1.x; o1.y = o1.y * corr + p * v1.y;
        o1.z = o1.z * corr + p * v1.z; o1.w = o1.w * corr + p * v1.w;
        o2.x = o2.x * corr + p * v2.x; o2.y = o2.y * corr + p * v2.y;
        o2.z = o2.z * corr + p * v2.z; o2.w = o2.w * corr + p * v2.w;
        o3.x = o3.x * corr + p * v3.x; o3.y = o3.y * corr + p * v3.y;
        o3.z = o3.z * corr + p * v3.z; o3.w = o3.w * corr + p * v3.w;
        m = mn;
    }
    float invl = 1.f / l;
    o0.x *= invl; o0.y *= invl; o0.z *= invl; o0.w *= invl;
    o1.x *= invl; o1.y *= invl; o1.z *= invl; o1.w *= invl;
    o2.x *= invl; o2.y *= invl; o2.z *= invl; o2.w *= invl;
    o3.x *= invl; o3.y *= invl; o3.z *= invl; o3.w *= invl;
    *(float4*)(o + base + (long)t * HH + 0)  = o0;
    *(float4*)(o + base + (long)t * HH + 4)  = o1;
    *(float4*)(o + base + (long)t * HH + 8)  = o2;
    *(float4*)(o + base + (long)t * HH + 12) = o3;
}

// ---------------- kernel 4: output head predictions[b,t,v] ------------------
__global__ void __launch_bounds__(256) outhead_kernel(
    const float* __restrict__ o2,
    const float* __restrict__ outW, const float* __restrict__ outB,
    float* __restrict__ pred)
{
    int bt = blockIdx.x;
    int tid = threadIdx.x;
    int v = tid >> 2;     // 0..63
    int part = tid & 3;   // 0..3
    const float* row = o2 + ((long)v * BT + bt) * HH + part * 32;
    const float* w = outW + v * HH + part * 32;
    float acc = 0.f;
#pragma unroll 8
    for (int i = 0; i < 32; i++) acc += row[i] * w[i];
    acc += __shfl_xor_sync(0xffffffffu, acc, 1);
    acc += __shfl_xor_sync(0xffffffffu, acc, 2);
    if (part == 0) pred[bt * VV + v] = acc + outB[v];
}

// ---------------- launch ----------------------------------------------------
extern "C" void kernel_launch(void* const* d_in, const int* in_sizes, int n_in,
                              void* d_out, int out_size) {
    const float* x        = (const float*)d_in[0];
    const float* adjl     = (const float*)d_in[1];
    const float* var_emb  = (const float*)d_in[2];
    const float* temp_emb = (const float*)d_in[3];
    const float* mech_W   = (const float*)d_in[4];
    const float* mech_b   = (const float*)d_in[5];
    const float* ln_g     = (const float*)d_in[6];
    const float* ln_b     = (const float*)d_in[7];
    const float* Wq       = (const float*)d_in[8];
    const float* Wk       = (const float*)d_in[9];
    const float* Wv       = (const float*)d_in[10];
    const float* Wo       = (const float*)d_in[11];
    const float* bq       = (const float*)d_in[12];
    const float* bk       = (const float*)d_in[13];
    const float* bv       = (const float*)d_in[14];
    const float* bo       = (const float*)d_in[15];
    const float* out_W    = (const float*)d_in[16];
    const float* out_b    = (const float*)d_in[17];
    float* pred = (float*)d_out;

    float *adj, *z0, *z1, *qb, *kb, *vb, *ob;
    cudaGetSymbolAddress((void**)&adj, g_adj);
    cudaGetSymbolAddress((void**)&z0, g_z0);
    cudaGetSymbolAddress((void**)&z1, g_z1);
    cudaGetSymbolAddress((void**)&qb, g_qb);
    cudaGetSymbolAddress((void**)&kb, g_kb);
    cudaGetSymbolAddress((void**)&vb, g_vb);
    cudaGetSymbolAddress((void**)&ob, g_ob);

    int nadj = VV * VV * LP1;
    sigmoid_kernel<<<(nadj + 255) / 256, 256>>>(adjl, adj, nadj);
    causal_input_kernel<<<BT, 128>>>(x, var_emb, temp_emb, adj, z0);

    dim3 gg(BT / 64, VV);
    const long HS = (long)HH * HH;
    // mechanism: 3 x (Linear -> LN -> GELU)
    pv_gemm<true><<<gg, 256>>>(z0, mech_W + 0 * HS, NLL * HS, mech_b + 0 * HH, NLL * HH,
                               ln_g + 0 * HH, ln_b + 0 * HH, z1);
    pv_gemm<true><<<gg, 256>>>(z1, mech_W + 1 * HS, NLL * HS, mech_b + 1 * HH, NLL * HH,
                               ln_g + 1 * HH, ln_b + 1 * HH, z0);
    pv_gemm<true><<<gg, 256>>>(z0, mech_W + 2 * HS, NLL * HS, mech_b + 2 * HH, NLL * HH,
                               ln_g + 2 * HH, ln_b + 2 * HH, z1);
    // qkv projections
    pv_gemm<false><<<gg, 256>>>(z1, Wq, HS, bq, HH, nullptr, nullptr, qb);
    pv_gemm<false><<<gg, 256>>>(z1, Wk, HS, bk, HH, nullptr, nullptr, kb);
    pv_gemm<false><<<gg, 256>>>(z1, Wv, HS, bv, HH, nullptr, nullptr, vb);
    // attention
    attn_kernel<<<BB * VV * NHH, 256>>>(qb, kb, vb, ob);
    // output projection
    pv_gemm<false><<<gg, 256>>>(ob, Wo, HS, bo, HH, nullptr, nullptr, z0);
    // head
    outhead_kernel<<<BT, 256>>>(z0, out_W, out_b, pred);
}

// round 4
// speedup vs baseline: 1.3021x; 1.3021x over previous
#include <cuda_runtime.h>
#include <cuda_bf16.h>
#include <math.h>

#define BB 4
#define SS 256
#define VV 64
#define LP1 11
#define HH 128
#define NHH 8
#define DHH 16
#define NLL 3
#define BT 1024   // B*S

// ---------------- scratch (static device globals; no runtime allocation) ----
__device__ float g_adj[VV * VV * LP1];
__device__ float g_z0[(long)VV * BT * HH];
__device__ float g_z1[(long)VV * BT * HH];
__device__ float g_qb[(long)VV * BT * HH];
__device__ float g_kb[(long)VV * BT * HH];
__device__ float g_vb[(long)VV * BT * HH];
__device__ float g_ob[(long)VV * BT * HH];

// ---------------- kernel 0: sigmoid of adjacency logits ---------------------
__global__ void sigmoid_kernel(const float* __restrict__ logits, float* __restrict__ adj, int n) {
    int i = blockIdx.x * blockDim.x + threadIdx.x;
    if (i < n) {
        float x = logits[i];
        adj[i] = 1.f / (1.f + __expf(-x));
    }
}

// ---------------- kernel 1: causal input z[b,t,i,h] -------------------------
__global__ void __launch_bounds__(128) causal_input_kernel(
    const float* __restrict__ x,
    const float* __restrict__ var_emb,
    const float* __restrict__ temp_emb,
    const float* __restrict__ adj,
    float* __restrict__ z)
{
    __shared__ float xlag[VV][12];
    __shared__ float Asm[VV][65];
    __shared__ float Blsm[VV][12];

    int bt = blockIdx.x;
    int b = bt >> 8;
    int t = bt & 255;
    int tid = threadIdx.x;

    for (int i = tid; i < VV * LP1; i += 128) {
        int s = i / LP1, l = i % LP1;
        xlag[s][l] = (t >= l) ? x[(b * SS + (t - l)) * VV + s] : 0.f;
    }
    __syncthreads();

    for (int i = tid; i < VV * VV; i += 128) {
        int s = i >> 6, ii = i & 63;
        const float* ap = adj + (s * VV + ii) * LP1;
        float a = 0.f;
#pragma unroll
        for (int l = 0; l < LP1; l++) a += xlag[s][l] * ap[l];
        Asm[ii][s] = a;
    }
    for (int i = tid; i < VV * LP1; i += 128) {
        int ii = i / LP1, l = i % LP1;
        float a = 0.f;
#pragma unroll 8
        for (int s = 0; s < VV; s++) a += xlag[s][l] * adj[(s * VV + ii) * LP1 + l];
        Blsm[ii][l] = a;
    }
    __syncthreads();

    int h = tid;  // 128 threads == H
    for (int ii = 0; ii < VV; ii++) {
        float acc = 0.f;
#pragma unroll 8
        for (int s = 0; s < VV; s++) acc += Asm[ii][s] * var_emb[s * HH + h];
#pragma unroll
        for (int l = 0; l < LP1; l++) acc += Blsm[ii][l] * temp_emb[l * HH + h];
        z[((long)ii * BT + bt) * HH + h] = acc;
    }
}

// ---------------- kernel 2: per-variable GEMM, 128x128 tile, 8x8/thread -----
// in/out layout: [v][bt][h]. W per variable: [h_in][h_out].
template <bool LN_GELU>
__global__ void __launch_bounds__(256, 2) pv_gemm(
    const float* __restrict__ in,
    const float* __restrict__ Wb, long wStride,
    const float* __restrict__ biasB, int bStride,
    const float* __restrict__ gB, const float* __restrict__ betaB,
    float* __restrict__ out)
{
    __shared__ float At[16][132];   // [k][row] transposed A tile
    __shared__ float Bt[16][128];   // [k][col]

    int v = blockIdx.y;
    int row0 = blockIdx.x * 128;
    const float* W = Wb + (long)v * wStride;
    const float* inV = in + ((long)v * BT + row0) * HH;
    float* outV = out + ((long)v * BT + row0) * HH;
    const float* bias = biasB + (long)v * bStride;

    int tid = threadIdx.x;
    int rg = tid >> 4;   // 0..15 -> rows rg*8 .. rg*8+7
    int cg = tid & 15;   // 0..15 -> cols cg*8 .. cg*8+7

    // A global-load mapping: 2 float4 per thread along k
    int ar = tid >> 2;        // 0..63 (and +64)
    int ac = (tid & 3) * 4;   // k offset within tile
    // B global-load mapping: 2 float4 per thread along columns
    int br = tid >> 5;        // 0..7 (and +8)
    int bc = (tid & 31) * 4;

    float acc[8][8];
#pragma unroll
    for (int r = 0; r < 8; r++)
#pragma unroll
        for (int c = 0; c < 8; c++) acc[r][c] = 0.f;

    // prefetch k-tile 0
    float4 a0p = *(const float4*)&inV[ar * HH + ac];
    float4 a1p = *(const float4*)&inV[(ar + 64) * HH + ac];
    float4 b0p = *(const float4*)&W[br * HH + bc];
    float4 b1p = *(const float4*)&W[(br + 8) * HH + bc];

    for (int kt = 0; kt < 8; kt++) {
        __syncthreads();
        At[ac + 0][ar] = a0p.x; At[ac + 1][ar] = a0p.y;
        At[ac + 2][ar] = a0p.z; At[ac + 3][ar] = a0p.w;
        At[ac + 0][ar + 64] = a1p.x; At[ac + 1][ar + 64] = a1p.y;
        At[ac + 2][ar + 64] = a1p.z; At[ac + 3][ar + 64] = a1p.w;
        *(float4*)&Bt[br][bc]     = b0p;
        *(float4*)&Bt[br + 8][bc] = b1p;
        __syncthreads();

        if (kt < 7) {
            int ko = (kt + 1) * 16;
            a0p = *(const float4*)&inV[ar * HH + ko + ac];
            a1p = *(const float4*)&inV[(ar + 64) * HH + ko + ac];
            b0p = *(const float4*)&W[(ko + br) * HH + bc];
            b1p = *(const float4*)&W[(ko + br + 8) * HH + bc];
        }

#pragma unroll
        for (int kk = 0; kk < 16; kk++) {
            float4 af0 = *(const float4*)&At[kk][rg * 8];
            float4 af1 = *(const float4*)&At[kk][rg * 8 + 4];
            float4 bf0 = *(const float4*)&Bt[kk][cg * 8];
            float4 bf1 = *(const float4*)&Bt[kk][cg * 8 + 4];
            float av[8] = {af0.x, af0.y, af0.z, af0.w, af1.x, af1.y, af1.z, af1.w};
            float bv[8] = {bf0.x, bf0.y, bf0.z, bf0.w, bf1.x, bf1.y, bf1.z, bf1.w};
#pragma unroll
            for (int r = 0; r < 8; r++)
#pragma unroll
                for (int c = 0; c < 8; c++) acc[r][c] += av[r] * bv[c];
        }
    }

    int colBase = cg * 8;
    float bvals[8];
#pragma unroll
    for (int c = 0; c < 8; c++) bvals[c] = bias[colBase + c];
#pragma unroll
    for (int r = 0; r < 8; r++)
#pragma unroll
        for (int c = 0; c < 8; c++) acc[r][c] += bvals[c];

    if (LN_GELU) {
        const float* gp = gB + (long)v * bStride;
        const float* bp = betaB + (long)v * bStride;
        float gv[8], bev[8];
#pragma unroll
        for (int c = 0; c < 8; c++) { gv[c] = gp[colBase + c]; bev[c] = bp[colBase + c]; }
#pragma unroll
        for (int r = 0; r < 8; r++) {
            float sum = 0.f, sq = 0.f;
#pragma unroll
            for (int c = 0; c < 8; c++) { sum += acc[r][c]; sq += acc[r][c] * acc[r][c]; }
#pragma unroll
            for (int m = 1; m < 16; m <<= 1) {
                sum += __shfl_xor_sync(0xffffffffu, sum, m);
                sq  += __shfl_xor_sync(0xffffffffu, sq, m);
            }
            float mu = sum * (1.f / 128.f);
            float var = sq * (1.f / 128.f) - mu * mu;
            float inv = rsqrtf(var + 1e-5f);
#pragma unroll
            for (int c = 0; c < 8; c++) {
                float xn = (acc[r][c] - mu) * inv * gv[c] + bev[c];
                acc[r][c] = 0.5f * xn * (1.f + erff(xn * 0.70710678118654752f));
            }
        }
    }

#pragma unroll
    for (int r = 0; r < 8; r++) {
        float4 s0 = make_float4(acc[r][0], acc[r][1], acc[r][2], acc[r][3]);
        float4 s1 = make_float4(acc[r][4], acc[r][5], acc[r][6], acc[r][7]);
        *(float4*)&outV[(rg * 8 + r) * HH + colBase]     = s0;
        *(float4*)&outV[(rg * 8 + r) * HH + colBase + 4] = s1;
    }
}

// ---------------- kernel 3: attention per (b,v,head), shift-free softmax ----
// Scores here are O(few); softmax is shift-invariant, and exp() in fp32 is safe
// to |s|~80, so we drop the running max / correction chain entirely.
__global__ void __launch_bounds__(256) attn_kernel(
    const float* __restrict__ q, const float* __restrict__ k,
    const float* __restrict__ vv, float* __restrict__ o)
{
    __shared__ float4 K4[SS * 4];
    __shared__ float4 V4[SS * 4];

    int g = blockIdx.x;
    int b = g / (VV * NHH);
    int rem = g % (VV * NHH);
    int v = rem / NHH;
    int nh = rem % NHH;

    long base = ((long)v * BT + (long)b * SS) * HH + nh * DHH;
    int t = threadIdx.x;

#pragma unroll
    for (int d4 = 0; d4 < 4; d4++) {
        K4[t * 4 + d4] = *(const float4*)(k  + base + (long)t * HH + d4 * 4);
        V4[t * 4 + d4] = *(const float4*)(vv + base + (long)t * HH + d4 * 4);
    }
    float4 q0 = *(const float4*)(q + base + (long)t * HH + 0);
    float4 q1 = *(const float4*)(q + base + (long)t * HH + 4);
    float4 q2 = *(const float4*)(q + base + (long)t * HH + 8);
    float4 q3 = *(const float4*)(q + base + (long)t * HH + 12);
    __syncthreads();

    float l = 0.f;
    float4 o0 = {0,0,0,0}, o1 = {0,0,0,0}, o2 = {0,0,0,0}, o3 = {0,0,0,0};

#pragma unroll 2
    for (int j = 0; j < SS; j++) {
        float4 k0 = K4[j * 4 + 0], k1 = K4[j * 4 + 1], k2 = K4[j * 4 + 2], k3 = K4[j * 4 + 3];
        float s = q0.x*k0.x + q0.y*k0.y + q0.z*k0.z + q0.w*k0.w
                + q1.x*k1.x + q1.y*k1.y + q1.z*k1.z + q1.w*k1.w
                + q2.x*k2.x + q2.y*k2.y + q2.z*k2.z + q2.w*k2.w
                + q3.x*k3.x + q3.y*k3.y + q3.z*k3.z + q3.w*k3.w;
        float p = __expf(s * 0.25f);  // scale = 1/sqrt(16)
        l += p;
        float4 v0 = V4[j * 4 + 0], v1 = V4[j * 4 + 1], v2 = V4[j * 4 + 2], v3 = V4[j * 4 + 3];
        o0.x += p * v0.x; o0.y += p * v0.y; o0.z += p * v0.z; o0.w += p * v0.w;
        o1.x += p * v1.x; o1.y += p * v1.y; o1.z += p * v1.z; o1.w += p * v1.w;
        o2.x += p * v2.x; o2.y += p * v2.y; o2.z += p * v2.z; o2.w += p * v2.w;
        o3.x += p * v3.x; o3.y += p * v3.y; o3.z += p * v3.z; o3.w += p * v3.w;
    }
    float invl = 1.f / l;
    o0.x *= invl; o0.y *= invl; o0.z *= invl; o0.w *= invl;
    o1.x *= invl; o1.y *= invl; o1.z *= invl; o1.w *= invl;
    o2.x *= invl; o2.y *= invl; o2.z *= invl; o2.w *= invl;
    o3.x *= invl; o3.y *= invl; o3.z *= invl; o3.w *= invl;
    *(float4*)(o + base + (long)t * HH + 0)  = o0;
    *(float4*)(o + base + (long)t * HH + 4)  = o1;
    *(float4*)(o + base + (long)t * HH + 8)  = o2;
    *(float4*)(o + base + (long)t * HH + 12) = o3;
}

// ---------------- kernel 4: output head predictions[b,t,v] ------------------
__global__ void __launch_bounds__(256) outhead_kernel(
    const float* __restrict__ o2,
    const float* __restrict__ outW, const float* __restrict__ outB,
    float* __restrict__ pred)
{
    int bt = blockIdx.x;
    int tid = threadIdx.x;
    int v = tid >> 2;     // 0..63
    int part = tid & 3;   // 0..3
    const float* row = o2 + ((long)v * BT + bt) * HH + part * 32;
    const float* w = outW + v * HH + part * 32;
    float acc = 0.f;
#pragma unroll 8
    for (int i = 0; i < 32; i++) acc += row[i] * w[i];
    acc += __shfl_xor_sync(0xffffffffu, acc, 1);
    acc += __shfl_xor_sync(0xffffffffu, acc, 2);
    if (part == 0) pred[bt * VV + v] = acc + outB[v];
}

// ---------------- launch ----------------------------------------------------
extern "C" void kernel_launch(void* const* d_in, const int* in_sizes, int n_in,
                              void* d_out, int out_size) {
    const float* x        = (const float*)d_in[0];
    const float* adjl     = (const float*)d_in[1];
    const float* var_emb  = (const float*)d_in[2];
    const float* temp_emb = (const float*)d_in[3];
    const float* mech_W   = (const float*)d_in[4];
    const float* mech_b   = (const float*)d_in[5];
    const float* ln_g     = (const float*)d_in[6];
    const float* ln_b     = (const float*)d_in[7];
    const float* Wq       = (const float*)d_in[8];
    const float* Wk       = (const float*)d_in[9];
    const float* Wv       = (const float*)d_in[10];
    const float* Wo       = (const float*)d_in[11];
    const float* bq       = (const float*)d_in[12];
    const float* bk       = (const float*)d_in[13];
    const float* bv       = (const float*)d_in[14];
    const float* bo       = (const float*)d_in[15];
    const float* out_W    = (const float*)d_in[16];
    const float* out_b    = (const float*)d_in[17];
    float* pred = (float*)d_out;

    float *adj, *z0, *z1, *qb, *kb, *vb, *ob;
    cudaGetSymbolAddress((void**)&adj, g_adj);
    cudaGetSymbolAddress((void**)&z0, g_z0);
    cudaGetSymbolAddress((void**)&z1, g_z1);
    cudaGetSymbolAddress((void**)&qb, g_qb);
    cudaGetSymbolAddress((void**)&kb, g_kb);
    cudaGetSymbolAddress((void**)&vb, g_vb);
    cudaGetSymbolAddress((void**)&ob, g_ob);

    int nadj = VV * VV * LP1;
    sigmoid_kernel<<<(nadj + 255) / 256, 256>>>(adjl, adj, nadj);
    causal_input_kernel<<<BT, 128>>>(x, var_emb, temp_emb, adj, z0);

    dim3 gg(BT / 128, VV);
    const long HS = (long)HH * HH;
    // mechanism: 3 x (Linear -> LN -> GELU)
    pv_gemm<true><<<gg, 256>>>(z0, mech_W + 0 * HS, NLL * HS, mech_b + 0 * HH, NLL * HH,
                               ln_g + 0 * HH, ln_b + 0 * HH, z1);
    pv_gemm<true><<<gg, 256>>>(z1, mech_W + 1 * HS, NLL * HS, mech_b + 1 * HH, NLL * HH,
                               ln_g + 1 * HH, ln_b + 1 * HH, z0);
    pv_gemm<true><<<gg, 256>>>(z0, mech_W + 2 * HS, NLL * HS, mech_b + 2 * HH, NLL * HH,
                               ln_g + 2 * HH, ln_b + 2 * HH, z1);
    // qkv projections
    pv_gemm<false><<<gg, 256>>>(z1, Wq, HS, bq, HH, nullptr, nullptr, qb);
    pv_gemm<false><<<gg, 256>>>(z1, Wk, HS, bk, HH, nullptr, nullptr, kb);
    pv_gemm<false><<<gg, 256>>>(z1, Wv, HS, bv, HH, nullptr, nullptr, vb);
    // attention
    attn_kernel<<<BB * VV * NHH, 256>>>(qb, kb, vb, ob);
    // output projection
    pv_gemm<false><<<gg, 256>>>(ob, Wo, HS, bo, HH, nullptr, nullptr, z0);
    // head
    outhead_kernel<<<BT, 256>>>(z0, out_W, out_b, pred);
}

// round 5
// speedup vs baseline: 1.3893x; 1.0670x over previous
#include <cuda_runtime.h>
#include <cuda_bf16.h>
#include <mma.h>
#include <math.h>

using namespace nvcuda;

#define BB 4
#define SS 256
#define VV 64
#define LP1 11
#define HH 128
#define NHH 8
#define DHH 16
#define NLL 3
#define BT 1024   // B*S

// ---------------- scratch (static device globals; no runtime allocation) ----
__device__ float g_adj[VV * VV * LP1];
__device__ float g_z0[(long)VV * BT * HH];
__device__ float g_z1[(long)VV * BT * HH];
__device__ float g_qb[(long)VV * BT * HH];
__device__ float g_kb[(long)VV * BT * HH];
__device__ float g_vb[(long)VV * BT * HH];
__device__ float g_ob[(long)VV * BT * HH];

// ---------------- kernel 0: sigmoid of adjacency logits ---------------------
__global__ void sigmoid_kernel(const float* __restrict__ logits, float* __restrict__ adj, int n) {
    int i = blockIdx.x * blockDim.x + threadIdx.x;
    if (i < n) {
        float x = logits[i];
        adj[i] = 1.f / (1.f + __expf(-x));
    }
}

// ---------------- kernel 1: causal input z[b,t,i,h] -------------------------
__global__ void __launch_bounds__(128) causal_input_kernel(
    const float* __restrict__ x,
    const float* __restrict__ var_emb,
    const float* __restrict__ temp_emb,
    const float* __restrict__ adj,
    float* __restrict__ z)
{
    __shared__ float xlag[VV][12];
    __shared__ float Asm[VV][65];
    __shared__ float Blsm[VV][12];

    int bt = blockIdx.x;
    int b = bt >> 8;
    int t = bt & 255;
    int tid = threadIdx.x;

    for (int i = tid; i < VV * LP1; i += 128) {
        int s = i / LP1, l = i % LP1;
        xlag[s][l] = (t >= l) ? x[(b * SS + (t - l)) * VV + s] : 0.f;
    }
    __syncthreads();

    for (int i = tid; i < VV * VV; i += 128) {
        int s = i >> 6, ii = i & 63;
        const float* ap = adj + (s * VV + ii) * LP1;
        float a = 0.f;
#pragma unroll
        for (int l = 0; l < LP1; l++) a += xlag[s][l] * ap[l];
        Asm[ii][s] = a;
    }
    for (int i = tid; i < VV * LP1; i += 128) {
        int ii = i / LP1, l = i % LP1;
        float a = 0.f;
#pragma unroll 8
        for (int s = 0; s < VV; s++) a += xlag[s][l] * adj[(s * VV + ii) * LP1 + l];
        Blsm[ii][l] = a;
    }
    __syncthreads();

    int h = tid;  // 128 threads == H
    for (int ii = 0; ii < VV; ii++) {
        float acc = 0.f;
#pragma unroll 8
        for (int s = 0; s < VV; s++) acc += Asm[ii][s] * var_emb[s * HH + h];
#pragma unroll
        for (int l = 0; l < LP1; l++) acc += Blsm[ii][l] * temp_emb[l * HH + h];
        z[((long)ii * BT + bt) * HH + h] = acc;
    }
}

// ---------------- kernel 2: per-variable GEMM on tensor cores ---------------
// Split-bf16 3-product compensation: a*b ~= ah*bh + ah*bl + al*bh, fp32 accum.
// in/out layout: [v][bt][h]. W per variable: [h_in][h_out].
// Block tile 128x128x128, 8 warps (2 row-groups x 4 col-groups), wmma 16x16x16.
#define A_LD 40     // 32 k + pad (bf16 elems; 80B rows, 16B aligned)
#define B_LD 136    // 128 n + pad
#define E_LD 132    // epilogue fp32 ld

// dyn smem layout (bytes):
//   [0      .. 10240)  A_hi  (128 x A_LD bf16)
//   [10240  .. 20480)  A_lo
//   [20480  .. 29184)  B_hi  (32 x B_LD bf16)
//   [29184  .. 37888)  B_lo
// epilogue (after final sync, overlays everything):
//   [0 .. 67584)       Esm   (128 x E_LD fp32)
#define PV_SMEM_BYTES 67584

template <bool LN_GELU>
__global__ void __launch_bounds__(256, 2) pv_gemm(
    const float* __restrict__ in,
    const float* __restrict__ Wb, long wStride,
    const float* __restrict__ biasB, int bStride,
    const float* __restrict__ gB, const float* __restrict__ betaB,
    float* __restrict__ out)
{
    extern __shared__ char smem[];
    __nv_bfloat16* Ah = (__nv_bfloat16*)smem;
    __nv_bfloat16* Al = (__nv_bfloat16*)(smem + 10240);
    __nv_bfloat16* Bh = (__nv_bfloat16*)(smem + 20480);
    __nv_bfloat16* Bl = (__nv_bfloat16*)(smem + 29184);
    float* Esm = (float*)smem;

    int v = blockIdx.y;
    int row0 = blockIdx.x * 128;
    const float* W = Wb + (long)v * wStride;
    const float* inV = in + ((long)v * BT + row0) * HH;
    float* outV = out + ((long)v * BT + row0) * HH;
    const float* bias = biasB + (long)v * bStride;

    int tid = threadIdx.x;
    int w = tid >> 5;
    int wr = w >> 2;      // 0..1 -> rows wr*64
    int wc = w & 3;       // 0..3 -> cols wc*32

    // conversion-stage mappings
    int arow = tid >> 1;             // 0..127
    int akb  = (tid & 1) * 16;       // k offset 0/16
    int brow = tid >> 3;             // 0..31 (k)
    int bcb  = (tid & 7) * 16;       // col offset

    wmma::fragment<wmma::accumulator, 16, 16, 16, float> acc[4][2];
#pragma unroll
    for (int i = 0; i < 4; i++)
#pragma unroll
        for (int j = 0; j < 2; j++) wmma::fill_fragment(acc[i][j], 0.f);

    for (int kt = 0; kt < 4; kt++) {
        __syncthreads();
        // ---- stage + split-convert A chunk (128 x 32) ----
#pragma unroll
        for (int jj = 0; jj < 4; jj++) {
            float4 x = *(const float4*)&inV[arow * HH + kt * 32 + akb + jj * 4];
            float xs[4] = {x.x, x.y, x.z, x.w};
            __nv_bfloat16 h[4], l[4];
#pragma unroll
            for (int c = 0; c < 4; c++) {
                h[c] = __float2bfloat16(xs[c]);
                l[c] = __float2bfloat16(xs[c] - __bfloat162float(h[c]));
            }
            int o = arow * A_LD + akb + jj * 4;
            *(__nv_bfloat162*)&Ah[o]     = __nv_bfloat162{h[0], h[1]};
            *(__nv_bfloat162*)&Ah[o + 2] = __nv_bfloat162{h[2], h[3]};
            *(__nv_bfloat162*)&Al[o]     = __nv_bfloat162{l[0], l[1]};
            *(__nv_bfloat162*)&Al[o + 2] = __nv_bfloat162{l[2], l[3]};
        }
        // ---- stage + split-convert B chunk (32 x 128) ----
#pragma unroll
        for (int jj = 0; jj < 4; jj++) {
            float4 x = *(const float4*)&W[(kt * 32 + brow) * HH + bcb + jj * 4];
            float xs[4] = {x.x, x.y, x.z, x.w};
            __nv_bfloat16 h[4], l[4];
#pragma unroll
            for (int c = 0; c < 4; c++) {
                h[c] = __float2bfloat16(xs[c]);
                l[c] = __float2bfloat16(xs[c] - __bfloat162float(h[c]));
            }
            int o = brow * B_LD + bcb + jj * 4;
            *(__nv_bfloat162*)&Bh[o]     = __nv_bfloat162{h[0], h[1]};
            *(__nv_bfloat162*)&Bh[o + 2] = __nv_bfloat162{h[2], h[3]};
            *(__nv_bfloat162*)&Bl[o]     = __nv_bfloat162{l[0], l[1]};
            *(__nv_bfloat162*)&Bl[o + 2] = __nv_bfloat162{l[2], l[3]};
        }
        __syncthreads();

        // ---- tensor-core mainloop over this k-chunk (2 ksteps of 16) ----
#pragma unroll
        for (int ks = 0; ks < 2; ks++) {
            wmma::fragment<wmma::matrix_a, 16, 16, 16, __nv_bfloat16, wmma::row_major> afh[4], afl[4];
            wmma::fragment<wmma::matrix_b, 16, 16, 16, __nv_bfloat16, wmma::row_major> bfh[2], bfl[2];
#pragma unroll
            for (int i = 0; i < 4; i++) {
                wmma::load_matrix_sync(afh[i], &Ah[(wr * 64 + i * 16) * A_LD + ks * 16], A_LD);
                wmma::load_matrix_sync(afl[i], &Al[(wr * 64 + i * 16) * A_LD + ks * 16], A_LD);
            }
#pragma unroll
            for (int j = 0; j < 2; j++) {
                wmma::load_matrix_sync(bfh[j], &Bh[(ks * 16) * B_LD + wc * 32 + j * 16], B_LD);
                wmma::load_matrix_sync(bfl[j], &Bl[(ks * 16) * B_LD + wc * 32 + j * 16], B_LD);
            }
#pragma unroll
            for (int i = 0; i < 4; i++)
#pragma unroll
                for (int j = 0; j < 2; j++) {
                    wmma::mma_sync(acc[i][j], afh[i], bfh[j], acc[i][j]);
                    wmma::mma_sync(acc[i][j], afh[i], bfl[j], acc[i][j]);
                    wmma::mma_sync(acc[i][j], afl[i], bfh[j], acc[i][j]);
                }
        }
    }

    // ---- epilogue: dump accumulators to smem, then bias (+LN+GELU) ----
    __syncthreads();
#pragma unroll
    for (int i = 0; i < 4; i++)
#pragma unroll
        for (int j = 0; j < 2; j++)
            wmma::store_matrix_sync(&Esm[(wr * 64 + i * 16) * E_LD + wc * 32 + j * 16],
                                    acc[i][j], E_LD, wmma::mem_row_major);
    __syncthreads();

    int row = tid >> 1;
    int ch = (tid & 1) * 64;
    const float* er = Esm + row * E_LD + ch;
    float vals[64];
#pragma unroll
    for (int i = 0; i < 16; i++) {
        float4 x = *(const float4*)&er[i * 4];
        vals[i * 4 + 0] = x.x; vals[i * 4 + 1] = x.y;
        vals[i * 4 + 2] = x.z; vals[i * 4 + 3] = x.w;
    }
#pragma unroll
    for (int i = 0; i < 64; i++) vals[i] += bias[ch + i];

    if (LN_GELU) {
        const float* gp = gB + (long)v * bStride;
        const float* bp = betaB + (long)v * bStride;
        float sum = 0.f, sq = 0.f;
#pragma unroll
        for (int i = 0; i < 64; i++) { sum += vals[i]; sq += vals[i] * vals[i]; }
        sum += __shfl_xor_sync(0xffffffffu, sum, 1);
        sq  += __shfl_xor_sync(0xffffffffu, sq, 1);
        float mu = sum * (1.f / 128.f);
        float var = sq * (1.f / 128.f) - mu * mu;
        float inv = rsqrtf(var + 1e-5f);
#pragma unroll
        for (int i = 0; i < 64; i++) {
            float xn = (vals[i] - mu) * inv * gp[ch + i] + bp[ch + i];
            vals[i] = 0.5f * xn * (1.f + erff(xn * 0.70710678118654752f));
        }
    }

#pragma unroll
    for (int i = 0; i < 16; i++) {
        float4 s = make_float4(vals[i * 4], vals[i * 4 + 1], vals[i * 4 + 2], vals[i * 4 + 3]);
        *(float4*)&outV[row * HH + ch + i * 4] = s;
    }
}

// ---------------- kernel 3: attention per (b,v,head), shift-free softmax ----
__global__ void __launch_bounds__(256) attn_kernel(
    const float* __restrict__ q, const float* __restrict__ k,
    const float* __restrict__ vv, float* __restrict__ o)
{
    __shared__ float4 K4[SS * 4];
    __shared__ float4 V4[SS * 4];

    int g = blockIdx.x;
    int b = g / (VV * NHH);
    int rem = g % (VV * NHH);
    int v = rem / NHH;
    int nh = rem % NHH;

    long base = ((long)v * BT + (long)b * SS) * HH + nh * DHH;
    int t = threadIdx.x;

#pragma unroll
    for (int d4 = 0; d4 < 4; d4++) {
        K4[t * 4 + d4] = *(const float4*)(k  + base + (long)t * HH + d4 * 4);
        V4[t * 4 + d4] = *(const float4*)(vv + base + (long)t * HH + d4 * 4);
    }
    float4 q0 = *(const float4*)(q + base + (long)t * HH + 0);
    float4 q1 = *(const float4*)(q + base + (long)t * HH + 4);
    float4 q2 = *(const float4*)(q + base + (long)t * HH + 8);
    float4 q3 = *(const float4*)(q + base + (long)t * HH + 12);
    __syncthreads();

    float l = 0.f;
    float4 o0 = {0,0,0,0}, o1 = {0,0,0,0}, o2 = {0,0,0,0}, o3 = {0,0,0,0};

#pragma unroll 2
    for (int j = 0; j < SS; j++) {
        float4 k0 = K4[j * 4 + 0], k1 = K4[j * 4 + 1], k2 = K4[j * 4 + 2], k3 = K4[j * 4 + 3];
        float s = q0.x*k0.x + q0.y*k0.y + q0.z*k0.z + q0.w*k0.w
                + q1.x*k1.x + q1.y*k1.y + q1.z*k1.z + q1.w*k1.w
                + q2.x*k2.x + q2.y*k2.y + q2.z*k2.z + q2.w*k2.w
                + q3.x*k3.x + q3.y*k3.y + q3.z*k3.z + q3.w*k3.w;
        float p = __expf(s * 0.25f);  // scale = 1/sqrt(16)
        l += p;
        float4 v0 = V4[j * 4 + 0], v1 = V4[j * 4 + 1], v2 = V4[j * 4 + 2], v3 = V4[j * 4 + 3];
        o0.x += p * v0.x; o0.y += p * v0.y; o0.z += p * v0.z; o0.w += p * v0.w;
        o1.x += p * v1.x; o1.y += p * v1.y; o1.z += p * v1.z; o1.w += p * v1.w;
        o2.x += p * v2.x; o2.y += p * v2.y; o2.z += p * v2.z; o2.w += p * v2.w;
        o3.x += p * v3.x; o3.y += p * v3.y; o3.z += p * v3.z; o3.w += p * v3.w;
    }
    float invl = 1.f / l;
    o0.x *= invl; o0.y *= invl; o0.z *= invl; o0.w *= invl;
    o1.x *= invl; o1.y *= invl; o1.z *= invl; o1.w *= invl;
    o2.x *= invl; o2.y *= invl; o2.z *= invl; o2.w *= invl;
    o3.x *= invl; o3.y *= invl; o3.z *= invl; o3.w *= invl;
    *(float4*)(o + base + (long)t * HH + 0)  = o0;
    *(float4*)(o + base + (long)t * HH + 4)  = o1;
    *(float4*)(o + base + (long)t * HH + 8)  = o2;
    *(float4*)(o + base + (long)t * HH + 12) = o3;
}

// ---------------- kernel 4: output head predictions[b,t,v] ------------------
__global__ void __launch_bounds__(256) outhead_kernel(
    const float* __restrict__ o2,
    const float* __restrict__ outW, const float* __restrict__ outB,
    float* __restrict__ pred)
{
    int bt = blockIdx.x;
    int tid = threadIdx.x;
    int v = tid >> 2;     // 0..63
    int part = tid & 3;   // 0..3
    const float* row = o2 + ((long)v * BT + bt) * HH + part * 32;
    const float* w = outW + v * HH + part * 32;
    float acc = 0.f;
#pragma unroll 8
    for (int i = 0; i < 32; i++) acc += row[i] * w[i];
    acc += __shfl_xor_sync(0xffffffffu, acc, 1);
    acc += __shfl_xor_sync(0xffffffffu, acc, 2);
    if (part == 0) pred[bt * VV + v] = acc + outB[v];
}

// ---------------- launch ----------------------------------------------------
extern "C" void kernel_launch(void* const* d_in, const int* in_sizes, int n_in,
                              void* d_out, int out_size) {
    const float* x        = (const float*)d_in[0];
    const float* adjl     = (const float*)d_in[1];
    const float* var_emb  = (const float*)d_in[2];
    const float* temp_emb = (const float*)d_in[3];
    const float* mech_W   = (const float*)d_in[4];
    const float* mech_b   = (const float*)d_in[5];
    const float* ln_g     = (const float*)d_in[6];
    const float* ln_b     = (const float*)d_in[7];
    const float* Wq       = (const float*)d_in[8];
    const float* Wk       = (const float*)d_in[9];
    const float* Wv       = (const float*)d_in[10];
    const float* Wo       = (const float*)d_in[11];
    const float* bq       = (const float*)d_in[12];
    const float* bk       = (const float*)d_in[13];
    const float* bv       = (const float*)d_in[14];
    const float* bo       = (const float*)d_in[15];
    const float* out_W    = (const float*)d_in[16];
    const float* out_b    = (const float*)d_in[17];
    float* pred = (float*)d_out;

    float *adj, *z0, *z1, *qb, *kb, *vb, *ob;
    cudaGetSymbolAddress((void**)&adj, g_adj);
    cudaGetSymbolAddress((void**)&z0, g_z0);
    cudaGetSymbolAddress((void**)&z1, g_z1);
    cudaGetSymbolAddress((void**)&qb, g_qb);
    cudaGetSymbolAddress((void**)&kb, g_kb);
    cudaGetSymbolAddress((void**)&vb, g_vb);
    cudaGetSymbolAddress((void**)&ob, g_ob);

    // opt in to >48KB dynamic smem for the tensor-core GEMM (host-side
    // attribute set, not a stream op; safe under graph capture)
    static bool attr_done = false;
    if (!attr_done) {
        cudaFuncSetAttribute(pv_gemm<true>,  cudaFuncAttributeMaxDynamicSharedMemorySize, PV_SMEM_BYTES);
        cudaFuncSetAttribute(pv_gemm<false>, cudaFuncAttributeMaxDynamicSharedMemorySize, PV_SMEM_BYTES);
        attr_done = true;
    }

    int nadj = VV * VV * LP1;
    sigmoid_kernel<<<(nadj + 255) / 256, 256>>>(adjl, adj, nadj);
    causal_input_kernel<<<BT, 128>>>(x, var_emb, temp_emb, adj, z0);

    dim3 gg(BT / 128, VV);
    const long HS = (long)HH * HH;
    // mechanism: 3 x (Linear -> LN -> GELU)
    pv_gemm<true><<<gg, 256, PV_SMEM_BYTES>>>(z0, mech_W + 0 * HS, NLL * HS, mech_b + 0 * HH, NLL * HH,
                               ln_g + 0 * HH, ln_b + 0 * HH, z1);
    pv_gemm<true><<<gg, 256, PV_SMEM_BYTES>>>(z1, mech_W + 1 * HS, NLL * HS, mech_b + 1 * HH, NLL * HH,
                               ln_g + 1 * HH, ln_b + 1 * HH, z0);
    pv_gemm<true><<<gg, 256, PV_SMEM_BYTES>>>(z0, mech_W + 2 * HS, NLL * HS, mech_b + 2 * HH, NLL * HH,
                               ln_g + 2 * HH, ln_b + 2 * HH, z1);
    // qkv projections
    pv_gemm<false><<<gg, 256, PV_SMEM_BYTES>>>(z1, Wq, HS, bq, HH, nullptr, nullptr, qb);
    pv_gemm<false><<<gg, 256, PV_SMEM_BYTES>>>(z1, Wk, HS, bk, HH, nullptr, nullptr, kb);
    pv_gemm<false><<<gg, 256, PV_SMEM_BYTES>>>(z1, Wv, HS, bv, HH, nullptr, nullptr, vb);
    // attention
    attn_kernel<<<BB * VV * NHH, 256>>>(qb, kb, vb, ob);
    // output projection
    pv_gemm<false><<<gg, 256, PV_SMEM_BYTES>>>(ob, Wo, HS, bo, HH, nullptr, nullptr, z0);
    // head
    outhead_kernel<<<BT, 256>>>(z0, out_W, out_b, pred);
}

// round 10
// speedup vs baseline: 1.5793x; 1.1368x over previous
#include <cuda_runtime.h>
#include <cuda_bf16.h>
#include <mma.h>
#include <math.h>
#include <stdint.h>

using namespace nvcuda;

#define BB 4
#define SS 256
#define VV 64
#define LP1 11
#define HH 128
#define NHH 8
#define DHH 16
#define NLL 3
#define BT 1024   // B*S
#define HS (HH * HH)

typedef unsigned long long u64;

// ---------------- scratch (static device globals; no runtime allocation) ----
__device__ float g_adj[VV * VV * LP1];
__device__ __nv_bfloat16 g_Whi[7L * VV * HS];
__device__ __nv_bfloat16 g_Wlo[7L * VV * HS];
__device__ __nv_bfloat16 g_zhi0[(long)VV * BT * HH];
__device__ __nv_bfloat16 g_zlo0[(long)VV * BT * HH];
__device__ __nv_bfloat16 g_zhi1[(long)VV * BT * HH];
__device__ __nv_bfloat16 g_zlo1[(long)VV * BT * HH];
__device__ __nv_bfloat16 g_ohi[(long)VV * BT * HH];
__device__ __nv_bfloat16 g_olo[(long)VV * BT * HH];
__device__ float g_qb[(long)VV * BT * HH];
__device__ float g_kb[(long)VV * BT * HH];
__device__ float g_vb[(long)VV * BT * HH];
__device__ float g_z0[(long)VV * BT * HH];

// ---------------- packed f32x2 helpers --------------------------------------
__device__ __forceinline__ void fma2(u64& d, u64 a, u64 b) {
    asm("fma.rn.f32x2 %0, %1, %2, %3;" : "=l"(d) : "l"(a), "l"(b), "l"(d));
}
__device__ __forceinline__ u64 add2(u64 a, u64 b) {
    u64 r; asm("add.rn.f32x2 %0, %1, %2;" : "=l"(r) : "l"(a), "l"(b)); return r;
}
__device__ __forceinline__ u64 pack2(float lo, float hi) {
    u64 r; asm("mov.b64 %0, {%1, %2};" : "=l"(r) : "f"(lo), "f"(hi)); return r;
}
__device__ __forceinline__ void unpack2(u64 v, float& lo, float& hi) {
    asm("mov.b64 {%0, %1}, %2;" : "=f"(lo), "=f"(hi) : "l"(v));
}

#define CPA16(smaddr, gptr) \
    asm volatile("cp.async.cg.shared.global [%0], [%1], 16;" :: "r"(smaddr), "l"(gptr))

// ---------------- kernel 0: sigmoid of adjacency logits ---------------------
__global__ void sigmoid_kernel(const float* __restrict__ logits, float* __restrict__ adj, int n) {
    int i = blockIdx.x * blockDim.x + threadIdx.x;
    if (i < n) {
        float x = logits[i];
        adj[i] = 1.f / (1.f + __expf(-x));
    }
}

// ---------------- kernel 0b: split all weights to bf16 hi/lo ----------------
// mat order: mech0, mech1, mech2, Wq, Wk, Wv, Wo ; dst layout [mat][v][k][n]
__global__ void split_weights_kernel(
    const float* __restrict__ mechW, const float* __restrict__ Wq,
    const float* __restrict__ Wk, const float* __restrict__ Wv,
    const float* __restrict__ Wo,
    __nv_bfloat16* __restrict__ hi, __nv_bfloat16* __restrict__ lo)
{
    long i = (long)blockIdx.x * blockDim.x + threadIdx.x;
    if (i >= 7L * VV * HS) return;
    int mat = (int)(i / ((long)VV * HS));
    long rem = i % ((long)VV * HS);
    int v = (int)(rem / HS);
    int e = (int)(rem % HS);
    float x;
    if (mat < 3) x = mechW[((long)v * NLL + mat) * HS + e];
    else {
        const float* p = (mat == 3) ? Wq : (mat == 4) ? Wk : (mat == 5) ? Wv : Wo;
        x = p[(long)v * HS + e];
    }
    __nv_bfloat16 h = __float2bfloat16(x);
    hi[i] = h;
    lo[i] = __float2bfloat16(x - __bfloat162float(h));
}

// ---------------- kernel 1: causal input z[b,t,i,h] -> bf16 hi/lo -----------
__global__ void __launch_bounds__(128) causal_input_kernel(
    const float* __restrict__ x,
    const float* __restrict__ var_emb,
    const float* __restrict__ temp_emb,
    const float* __restrict__ adj,
    __nv_bfloat16* __restrict__ zHi, __nv_bfloat16* __restrict__ zLo)
{
    __shared__ float xlag[VV][12];
    __shared__ float Asm[VV][65];
    __shared__ float Blsm[VV][12];

    int bt = blockIdx.x;
    int b = bt >> 8;
    int t = bt & 255;
    int tid = threadIdx.x;

    for (int i = tid; i < VV * LP1; i += 128) {
        int s = i / LP1, l = i % LP1;
        xlag[s][l] = (t >= l) ? x[(b * SS + (t - l)) * VV + s] : 0.f;
    }
    __syncthreads();

    for (int i = tid; i < VV * VV; i += 128) {
        int s = i >> 6, ii = i & 63;
        const float* ap = adj + (s * VV + ii) * LP1;
        float a = 0.f;
#pragma unroll
        for (int l = 0; l < LP1; l++) a += xlag[s][l] * ap[l];
        Asm[ii][s] = a;
    }
    for (int i = tid; i < VV * LP1; i += 128) {
        int ii = i / LP1, l = i % LP1;
        float a = 0.f;
#pragma unroll 8
        for (int s = 0; s < VV; s++) a += xlag[s][l] * adj[(s * VV + ii) * LP1 + l];
        Blsm[ii][l] = a;
    }
    __syncthreads();

    int h = tid;  // 128 threads == H
    float acc[VV];
#pragma unroll
    for (int ii = 0; ii < VV; ii++) acc[ii] = 0.f;
    for (int s = 0; s < VV; s++) {
        float ve = var_emb[s * HH + h];
#pragma unroll
        for (int ii = 0; ii < VV; ii++) acc[ii] += Asm[ii][s] * ve;
    }
#pragma unroll
    for (int l = 0; l < LP1; l++) {
        float te = temp_emb[l * HH + h];
#pragma unroll
        for (int ii = 0; ii < VV; ii++) acc[ii] += Blsm[ii][l] * te;
    }
#pragma unroll 8
    for (int ii = 0; ii < VV; ii++) {
        long o = ((long)ii * BT + bt) * HH + h;
        __nv_bfloat16 hh = __float2bfloat16(acc[ii]);
        zHi[o] = hh;
        zLo[o] = __float2bfloat16(acc[ii] - __bfloat162float(hh));
    }
}

// ---------------- kernel 2: per-variable GEMM on tensor cores ---------------
// Pre-split bf16 hi/lo operands in gmem; 3-product compensation in fp32 accum.
// 128x128x128 block tile, 8 warps (2x4), wmma 16x16x16, cp.async double buffer.
#define A_LD 40     // 32 k + pad (bf16 elems)
#define B_LD 136    // 128 n + pad
#define E_LD 132    // epilogue fp32 ld
#define ABUF 20480  // A hi+lo bytes per buffer (128*A_LD*2 * 2)
#define BBUF 17408  // B hi+lo bytes per buffer (32*B_LD*2 * 2)
#define PV_SMEM_BYTES 75776   // 2*ABUF + 2*BBUF; epilogue overlay 67584 fits

template <bool LN_GELU, bool OUT_SPLIT>
__global__ void __launch_bounds__(256, 2) pv_gemm(
    const __nv_bfloat16* __restrict__ Ahi, const __nv_bfloat16* __restrict__ Alo,
    const __nv_bfloat16* __restrict__ Whi, const __nv_bfloat16* __restrict__ Wlo,
    const float* __restrict__ biasB, int bStride,
    const float* __restrict__ gB, const float* __restrict__ betaB,
    float* __restrict__ outF,
    __nv_bfloat16* __restrict__ outHi, __nv_bfloat16* __restrict__ outLo)
{
    extern __shared__ char smem[];
    float* Esm = (float*)smem;

    int v = blockIdx.y;
    int row0 = blockIdx.x * 128;
    const __nv_bfloat16* AhV = Ahi + ((long)v * BT + row0) * HH;
    const __nv_bfloat16* AlV = Alo + ((long)v * BT + row0) * HH;
    const __nv_bfloat16* WhV = Whi + (long)v * HS;
    const __nv_bfloat16* WlV = Wlo + (long)v * HS;
    const float* bias = biasB + (long)v * bStride;

    int tid = threadIdx.x;
    int w = tid >> 5;
    int wr = w >> 2;      // 0..1 -> rows wr*64
    int wc = w & 3;       // 0..3 -> cols wc*32

    unsigned int smem_u32;
    asm("{ .reg .u64 t0; cvta.to.shared.u64 t0, %1; cvt.u32.u64 %0, t0; }"
        : "=r"(smem_u32) : "l"(smem));

    // copy mappings: A chunk 128x32, B chunk 32x128, 16B per cp.async
    int tA_r = tid >> 2, tA_g = tid & 3;
    int tB_r = tid >> 4, tB_g = tid & 15;
    unsigned int aOff0 = (unsigned int)(tA_r * A_LD + tA_g * 8) * 2u;
    unsigned int aOff1 = (unsigned int)((tA_r + 64) * A_LD + tA_g * 8) * 2u;
    unsigned int bOff0 = (unsigned int)(tB_r * B_LD + tB_g * 8) * 2u;
    unsigned int bOff1 = (unsigned int)((tB_r + 16) * B_LD + tB_g * 8) * 2u;

    auto issue_chunk = [&](int kt, int buf) {
        unsigned int aBase = smem_u32 + buf * ABUF;
        unsigned int bBase = smem_u32 + 2 * ABUF + buf * BBUF;
        const __nv_bfloat16* gah = AhV + (long)tA_r * HH + kt * 32 + tA_g * 8;
        const __nv_bfloat16* gal = AlV + (long)tA_r * HH + kt * 32 + tA_g * 8;
        CPA16(aBase + aOff0, gah);
        CPA16(aBase + aOff1, gah + 64 * HH);
        CPA16(aBase + 10240 + aOff0, gal);
        CPA16(aBase + 10240 + aOff1, gal + 64 * HH);
        const __nv_bfloat16* gwh = WhV + (long)(kt * 32 + tB_r) * HH + tB_g * 8;
        const __nv_bfloat16* gwl = WlV + (long)(kt * 32 + tB_r) * HH + tB_g * 8;
        CPA16(bBase + bOff0, gwh);
        CPA16(bBase + bOff1, gwh + 16 * HH);
        CPA16(bBase + 8704 + bOff0, gwl);
        CPA16(bBase + 8704 + bOff1, gwl + 16 * HH);
        asm volatile("cp.async.commit_group;");
    };

    wmma::fragment<wmma::accumulator, 16, 16, 16, float> acc[4][2];
#pragma unroll
    for (int i = 0; i < 4; i++)
#pragma unroll
        for (int j = 0; j < 2; j++) wmma::fill_fragment(acc[i][j], 0.f);

    issue_chunk(0, 0);
    issue_chunk(1, 1);

#pragma unroll
    for (int kt = 0; kt < 4; kt++) {
        if (kt < 3) { asm volatile("cp.async.wait_group 1;" ::: "memory"); }
        else        { asm volatile("cp.async.wait_group 0;" ::: "memory"); }
        __syncthreads();

        int buf = kt & 1;
        const __nv_bfloat16* Ah = (const __nv_bfloat16*)(smem + buf * ABUF);
        const __nv_bfloat16* Al = (const __nv_bfloat16*)(smem + buf * ABUF + 10240);
        const __nv_bfloat16* Bh = (const __nv_bfloat16*)(smem + 2 * ABUF + buf * BBUF);
        const __nv_bfloat16* Bl = (const __nv_bfloat16*)(smem + 2 * ABUF + buf * BBUF + 8704);

#pragma unroll
        for (int ks = 0; ks < 2; ks++) {
            wmma::fragment<wmma::matrix_a, 16, 16, 16, __nv_bfloat16, wmma::row_major> afh[4], afl[4];
            wmma::fragment<wmma::matrix_b, 16, 16, 16, __nv_bfloat16, wmma::row_major> bfh[2], bfl[2];
#pragma unroll
            for (int i = 0; i < 4; i++) {
                wmma::load_matrix_sync(afh[i], &Ah[(wr * 64 + i * 16) * A_LD + ks * 16], A_LD);
                wmma::load_matrix_sync(afl[i], &Al[(wr * 64 + i * 16) * A_LD + ks * 16], A_LD);
            }
#pragma unroll
            for (int j = 0; j < 2; j++) {
                wmma::load_matrix_sync(bfh[j], &Bh[(ks * 16) * B_LD + wc * 32 + j * 16], B_LD);
                wmma::load_matrix_sync(bfl[j], &Bl[(ks * 16) * B_LD + wc * 32 + j * 16], B_LD);
            }
#pragma unroll
            for (int i = 0; i < 4; i++)
#pragma unroll
                for (int j = 0; j < 2; j++) {
                    wmma::mma_sync(acc[i][j], afh[i], bfh[j], acc[i][j]);
                    wmma::mma_sync(acc[i][j], afh[i], bfl[j], acc[i][j]);
                    wmma::mma_sync(acc[i][j], afl[i], bfh[j], acc[i][j]);
                }
        }
        __syncthreads();
        if (kt < 2) issue_chunk(kt + 2, buf);
    }

    // ---- epilogue: dump accumulators to smem, then bias (+LN+GELU) ----
#pragma unroll
    for (int i = 0; i < 4; i++)
#pragma unroll
        for (int j = 0; j < 2; j++)
            wmma::store_matrix_sync(&Esm[(wr * 64 + i * 16) * E_LD + wc * 32 + j * 16],
                                    acc[i][j], E_LD, wmma::mem_row_major);
    __syncthreads();

    int row = tid >> 1;
    int ch = (tid & 1) * 64;
    const float* er = Esm + row * E_LD + ch;
    float vals[64];
#pragma unroll
    for (int i = 0; i < 16; i++) {
        float4 x = *(const float4*)&er[i * 4];
        vals[i * 4 + 0] = x.x; vals[i * 4 + 1] = x.y;
        vals[i * 4 + 2] = x.z; vals[i * 4 + 3] = x.w;
    }
#pragma unroll
    for (int i = 0; i < 64; i++) vals[i] += bias[ch + i];

    if (LN_GELU) {
        const float* gp = gB + (long)v * bStride;
        const float* bp = betaB + (long)v * bStride;
        float sum = 0.f, sq = 0.f;
#pragma unroll
        for (int i = 0; i < 64; i++) { sum += vals[i]; sq += vals[i] * vals[i]; }
        sum += __shfl_xor_sync(0xffffffffu, sum, 1);
        sq  += __shfl_xor_sync(0xffffffffu, sq, 1);
        float mu = sum * (1.f / 128.f);
        float var = sq * (1.f / 128.f) - mu * mu;
        float inv = rsqrtf(var + 1e-5f);
#pragma unroll
        for (int i = 0; i < 64; i++) {
            float xn = (vals[i] - mu) * inv * gp[ch + i] + bp[ch + i];
            vals[i] = 0.5f * xn * (1.f + erff(xn * 0.70710678118654752f));
        }
    }

    long rowIdx = ((long)v * BT + row0 + row) * HH + ch;
    if (OUT_SPLIT) {
        __nv_bfloat16 hv[64], lv[64];
#pragma unroll
        for (int i = 0; i < 64; i++) {
            __nv_bfloat16 h = __float2bfloat16(vals[i]);
            hv[i] = h;
            lv[i] = __float2bfloat16(vals[i] - __bfloat162float(h));
        }
#pragma unroll
        for (int g = 0; g < 8; g++) {
            *(uint4*)&outHi[rowIdx + g * 8] = *(uint4*)&hv[g * 8];
            *(uint4*)&outLo[rowIdx + g * 8] = *(uint4*)&lv[g * 8];
        }
    } else {
#pragma unroll
        for (int i = 0; i < 16; i++) {
            float4 s = make_float4(vals[i * 4], vals[i * 4 + 1], vals[i * 4 + 2], vals[i * 4 + 3]);
            *(float4*)&outF[rowIdx + i * 4] = s;
        }
    }
}

// ---------------- kernel 3: attention, packed f32x2, shift-free softmax -----
__global__ void __launch_bounds__(256) attn_kernel(
    const float* __restrict__ q, const float* __restrict__ k,
    const float* __restrict__ vv,
    __nv_bfloat16* __restrict__ oHi, __nv_bfloat16* __restrict__ oLo)
{
    __shared__ ulonglong2 K2[SS * 4];
    __shared__ ulonglong2 V2[SS * 4];

    int g = blockIdx.x;
    int b = g / (VV * NHH);
    int rem = g % (VV * NHH);
    int v = rem / NHH;
    int nh = rem % NHH;

    long base = ((long)v * BT + (long)b * SS) * HH + nh * DHH;
    int t = threadIdx.x;

    const ulonglong2* kp = (const ulonglong2*)(k + base + (long)t * HH);
    const ulonglong2* vp = (const ulonglong2*)(vv + base + (long)t * HH);
#pragma unroll
    for (int d = 0; d < 4; d++) {
        K2[t * 4 + d] = kp[d];
        V2[t * 4 + d] = vp[d];
    }
    const ulonglong2* qp = (const ulonglong2*)(q + base + (long)t * HH);
    u64 q2[8];
#pragma unroll
    for (int d = 0; d < 4; d++) {
        ulonglong2 qa = qp[d];
        q2[d * 2] = qa.x; q2[d * 2 + 1] = qa.y;
    }
    __syncthreads();

    float l = 0.f;
    u64 o2[8];
#pragma unroll
    for (int i = 0; i < 8; i++) o2[i] = 0ull;

#pragma unroll 2
    for (int j = 0; j < SS; j++) {
        ulonglong2 ka = K2[j * 4 + 0], kb2 = K2[j * 4 + 1];
        ulonglong2 kc = K2[j * 4 + 2], kd = K2[j * 4 + 3];
        u64 acc0 = 0ull, acc1 = 0ull;
        fma2(acc0, q2[0], ka.x);  fma2(acc1, q2[1], ka.y);
        fma2(acc0, q2[2], kb2.x); fma2(acc1, q2[3], kb2.y);
        fma2(acc0, q2[4], kc.x);  fma2(acc1, q2[5], kc.y);
        fma2(acc0, q2[6], kd.x);  fma2(acc1, q2[7], kd.y);
        u64 accs = add2(acc0, acc1);
        float slo, shi;
        unpack2(accs, slo, shi);
        float p = __expf((slo + shi) * 0.25f);   // scale = 1/sqrt(16)
        l += p;
        u64 p2 = pack2(p, p);
        ulonglong2 va = V2[j * 4 + 0], vb2 = V2[j * 4 + 1];
        ulonglong2 vc = V2[j * 4 + 2], vd = V2[j * 4 + 3];
        fma2(o2[0], p2, va.x);  fma2(o2[1], p2, va.y);
        fma2(o2[2], p2, vb2.x); fma2(o2[3], p2, vb2.y);
        fma2(o2[4], p2, vc.x);  fma2(o2[5], p2, vc.y);
        fma2(o2[6], p2, vd.x);  fma2(o2[7], p2, vd.y);
    }

    float invl = 1.f / l;
    float of[16];
#pragma unroll
    for (int i = 0; i < 8; i++) {
        float lo, hi;
        unpack2(o2[i], lo, hi);
        of[i * 2] = lo * invl;
        of[i * 2 + 1] = hi * invl;
    }
    __nv_bfloat16 hv[16], lv[16];
#pragma unroll
    for (int i = 0; i < 16; i++) {
        __nv_bfloat16 h = __float2bfloat16(of[i]);
        hv[i] = h;
        lv[i] = __float2bfloat16(of[i] - __bfloat162float(h));
    }
    long obase = base + (long)t * HH;
    *(uint4*)&oHi[obase]     = *(uint4*)&hv[0];
    *(uint4*)&oHi[obase + 8] = *(uint4*)&hv[8];
    *(uint4*)&oLo[obase]     = *(uint4*)&lv[0];
    *(uint4*)&oLo[obase + 8] = *(uint4*)&lv[8];
}

// ---------------- kernel 4: output head predictions[b,t,v] ------------------
__global__ void __launch_bounds__(256) outhead_kernel(
    const float* __restrict__ o2,
    const float* __restrict__ outW, const float* __restrict__ outB,
    float* __restrict__ pred)
{
    int bt = blockIdx.x;
    int tid = threadIdx.x;
    int v = tid >> 2;     // 0..63
    int part = tid & 3;   // 0..3
    const float* row = o2 + ((long)v * BT + bt) * HH + part * 32;
    const float* w = outW + v * HH + part * 32;
    float acc = 0.f;
#pragma unroll 8
    for (int i = 0; i < 32; i++) acc += row[i] * w[i];
    acc += __shfl_xor_sync(0xffffffffu, acc, 1);
    acc += __shfl_xor_sync(0xffffffffu, acc, 2);
    if (part == 0) pred[bt * VV + v] = acc + outB[v];
}

// ---------------- launch ----------------------------------------------------
extern "C" void kernel_launch(void* const* d_in, const int* in_sizes, int n_in,
                              void* d_out, int out_size) {
    const float* x        = (const float*)d_in[0];
    const float* adjl     = (const float*)d_in[1];
    const float* var_emb  = (const float*)d_in[2];
    const float* temp_emb = (const float*)d_in[3];
    const float* mech_W   = (const float*)d_in[4];
    const float* mech_b   = (const float*)d_in[5];
    const float* ln_g     = (const float*)d_in[6];
    const float* ln_b     = (const float*)d_in[7];
    const float* Wq       = (const float*)d_in[8];
    const float* Wk       = (const float*)d_in[9];
    const float* Wv       = (const float*)d_in[10];
    const float* Wo       = (const float*)d_in[11];
    const float* bq       = (const float*)d_in[12];
    const float* bk       = (const float*)d_in[13];
    const float* bv       = (const float*)d_in[14];
    const float* bo       = (const float*)d_in[15];
    const float* out_W    = (const float*)d_in[16];
    const float* out_b    = (const float*)d_in[17];
    float* pred = (float*)d_out;

    float *adj, *qb, *kb, *vb, *z0;
    __nv_bfloat16 *Whi, *Wlo, *zhi0, *zlo0, *zhi1, *zlo1, *ohi, *olo;
    cudaGetSymbolAddress((void**)&adj, g_adj);
    cudaGetSymbolAddress((void**)&Whi, g_Whi);
    cudaGetSymbolAddress((void**)&Wlo, g_Wlo);
    cudaGetSymbolAddress((void**)&zhi0, g_zhi0);
    cudaGetSymbolAddress((void**)&zlo0, g_zlo0);
    cudaGetSymbolAddress((void**)&zhi1, g_zhi1);
    cudaGetSymbolAddress((void**)&zlo1, g_zlo1);
    cudaGetSymbolAddress((void**)&ohi, g_ohi);
    cudaGetSymbolAddress((void**)&olo, g_olo);
    cudaGetSymbolAddress((void**)&qb, g_qb);
    cudaGetSymbolAddress((void**)&kb, g_kb);
    cudaGetSymbolAddress((void**)&vb, g_vb);
    cudaGetSymbolAddress((void**)&z0, g_z0);

    static bool attr_done = false;
    if (!attr_done) {
        cudaFuncSetAttribute((const void*)pv_gemm<true, true>,
                             cudaFuncAttributeMaxDynamicSharedMemorySize, PV_SMEM_BYTES);
        cudaFuncSetAttribute((const void*)pv_gemm<false, false>,
                             cudaFuncAttributeMaxDynamicSharedMemorySize, PV_SMEM_BYTES);
        attr_done = true;
    }

    int nadj = VV * VV * LP1;
    sigmoid_kernel<<<(nadj + 255) / 256, 256>>>(adjl, adj, nadj);

    long nw = 7L * VV * HS;
    split_weights_kernel<<<(int)((nw + 255) / 256), 256>>>(mech_W, Wq, Wk, Wv, Wo, Whi, Wlo);

    causal_input_kernel<<<BT, 128>>>(x, var_emb, temp_emb, adj, zhi0, zlo0);

    dim3 gg(BT / 128, VV);
    const long WSZ = (long)VV * HS;
    // mechanism: 3 x (Linear -> LN -> GELU), split outputs
    pv_gemm<true, true><<<gg, 256, PV_SMEM_BYTES>>>(
        zhi0, zlo0, Whi + 0 * WSZ, Wlo + 0 * WSZ, mech_b + 0 * HH, NLL * HH,
        ln_g + 0 * HH, ln_b + 0 * HH, nullptr, zhi1, zlo1);
    pv_gemm<true, true><<<gg, 256, PV_SMEM_BYTES>>>(
        zhi1, zlo1, Whi + 1 * WSZ, Wlo + 1 * WSZ, mech_b + 1 * HH, NLL * HH,
        ln_g + 1 * HH, ln_b + 1 * HH, nullptr, zhi0, zlo0);
    pv_gemm<true, true><<<gg, 256, PV_SMEM_BYTES>>>(
        zhi0, zlo0, Whi + 2 * WSZ, Wlo + 2 * WSZ, mech_b + 2 * HH, NLL * HH,
        ln_g + 2 * HH, ln_b + 2 * HH, nullptr, zhi1, zlo1);
    // qkv projections, fp32 outputs for attention
    pv_gemm<false, false><<<gg, 256, PV_SMEM_BYTES>>>(
        zhi1, zlo1, Whi + 3 * WSZ, Wlo + 3 * WSZ, bq, HH,
        nullptr, nullptr, qb, nullptr, nullptr);
    pv_gemm<false, false><<<gg, 256, PV_SMEM_BYTES>>>(
        zhi1, zlo1, Whi + 4 * WSZ, Wlo + 4 * WSZ, bk, HH,
        nullptr, nullptr, kb, nullptr, nullptr);
    pv_gemm<false, false><<<gg, 256, PV_SMEM_BYTES>>>(
        zhi1, zlo1, Whi + 5 * WSZ, Wlo + 5 * WSZ, bv, HH,
        nullptr, nullptr, vb, nullptr, nullptr);
    // attention, split output
    attn_kernel<<<BB * VV * NHH, 256>>>(qb, kb, vb, ohi, olo);
    // output projection
    pv_gemm<false, false><<<gg, 256, PV_SMEM_BYTES>>>(
        ohi, olo, Whi + 6 * WSZ, Wlo + 6 * WSZ, bo, HH,
        nullptr, nullptr, z0, nullptr, nullptr);
    // head
    outhead_kernel<<<BT, 256>>>(z0, out_W, out_b, pred);
}